// round 5
// baseline (speedup 1.0000x reference)
#include <cuda_runtime.h>
#include <cstddef>

#define Bn 16
#define Nn 2048
#define Cn 128
#define NP 512
#define CIN 131
#define CPW2 160
#define PROW 132
#define NROWS (3*Bn*NP)
#define NTILES 4096

__device__ float g_featT[Bn*Nn*Cn];      // features transposed (B,N,C)
__device__ float g_pooled[NROWS*PROW];   // pooled rows (row = s*8192 + b*512 + p)
__device__ volatile int g_prog[Bn];      // FPS progress per batch (zero-init)
__device__ int g_tick = 0;               // transpose tile ticket
__device__ volatile int g_tdone = 0;     // transpose tiles completed

// ---------------------------------------------------------------------------
// K_MAIN (fused): blocks [0,16) = FPS producers (publish progress);
// blocks [16,16+8192) = per-center MSG consumers. MSG blocks first work-steal
// feature-transpose tiles, then spin (nanosleep) until their center is ready.
// ---------------------------------------------------------------------------
__global__ __launch_bounds__(256) void k_main(const float* __restrict__ xyz,
                                              const float* __restrict__ feat,
                                              const float* __restrict__ W1,
                                              const float* __restrict__ b1,
                                              const float* __restrict__ W2,
                                              const float* __restrict__ b2,
                                              float* __restrict__ out_xyz) {
    int tid = threadIdx.x, lane = tid & 31, w = tid >> 5;

    if (blockIdx.x < 16) {
        // ================= FPS (one block per batch, 8 pts/thread) =========
        __shared__ float xs[Nn], ys[Nn], zs[Nn];
        __shared__ unsigned rvb[2][8];
        __shared__ int      rib[2][8];
        int b = blockIdx.x;
        const float* src = xyz + (size_t)b * Nn * 3;
        for (int t = tid; t < Nn; t += 256) {
            xs[t] = src[t*3 + 0]; ys[t] = src[t*3 + 1]; zs[t] = src[t*3 + 2];
        }
        __syncthreads();
        float X[8], Y[8], Z[8], D[8];
#pragma unroll
        for (int q = 0; q < 8; ++q) {
            int i = tid*8 + q;
            X[q] = xs[i]; Y[q] = ys[i]; Z[q] = zs[i];
            D[q] = 1e10f;
        }
        int last = 0;
        if (tid == 0) {
            out_xyz[(size_t)b*NP*3 + 0] = xs[0];
            out_xyz[(size_t)b*NP*3 + 1] = ys[0];
            out_xyz[(size_t)b*NP*3 + 2] = zs[0];
        }
        for (int it = 1; it < NP; ++it) {
            float px = xs[last], py = ys[last], pz = zs[last];
#pragma unroll
            for (int q = 0; q < 8; ++q) {
                float ax = X[q] - px, ay = Y[q] - py, az = Z[q] - pz;
                float dd = __fadd_rn(__fadd_rn(__fmul_rn(ax,ax), __fmul_rn(ay,ay)),
                                     __fmul_rn(az,az));
                D[q] = fminf(D[q], dd);
            }
            float va = D[0]; int ia = 0;
            if (D[1] > va) { va = D[1]; ia = 1; }
            float vb = D[2]; int ib = 2;
            if (D[3] > vb) { vb = D[3]; ib = 3; }
            float vc = D[4]; int ic = 4;
            if (D[5] > vc) { vc = D[5]; ic = 5; }
            float vd = D[6]; int id_ = 6;
            if (D[7] > vd) { vd = D[7]; id_ = 7; }
            if (vb > va) { va = vb; ia = ib; }
            if (vd > vc) { vc = vd; ic = id_; }
            if (vc > va) { va = vc; ia = ic; }
            unsigned bits = __float_as_uint(va);
            unsigned m = __reduce_max_sync(0xffffffffu, bits);
            unsigned bal = __ballot_sync(0xffffffffu, bits == m);
            int srcl = __ffs(bal) - 1;
            int lloc = __shfl_sync(0xffffffffu, ia, srcl);
            int bufi = it & 1;
            if (lane == 0) {
                rvb[bufi][w] = m;
                rib[bufi][w] = (w*32 + srcl)*8 + lloc;
            }
            __syncthreads();
            int j = lane & 7;
            unsigned v2 = rvb[bufi][j];
            int      i2 = rib[bufi][j];
            unsigned m2 = __reduce_max_sync(0xffffffffu, v2);
            unsigned b2_ = __ballot_sync(0xffffffffu, v2 == m2);
            int s2 = __ffs(b2_) - 1;
            last = __shfl_sync(0xffffffffu, i2, s2);
            if (tid == 0) {
                out_xyz[(size_t)(b*NP + it)*3 + 0] = xs[last];
                out_xyz[(size_t)(b*NP + it)*3 + 1] = ys[last];
                out_xyz[(size_t)(b*NP + it)*3 + 2] = zs[last];
                if ((it & 3) == 3) {            // publish every 4 iters (511 incl.)
                    __threadfence();
                    g_prog[b] = it + 1;
                }
            }
        }
        return;
    }

    // ================= MSG block (one per center), 256 threads =============
    __shared__ float W2s[32*CPW2];        // first 1056 floats double as transpose tile
    __shared__ float b2s[CPW2];
    __shared__ float W1s[320];
    __shared__ float b1s[32];
    __shared__ int   idx_sh[96];
    __shared__ float h1buf[8*32*4];
    __shared__ int   pooled_sh[3*132];
    __shared__ int   tno;

    int blk = blockIdx.x - 16;
    int b = blk >> 9, p = blk & 511;
    const float* bp = xyz + (size_t)b * Nn * 3;

    // ---- work-steal transpose tiles (uses W2s[0..1055] as the 32x33 tile)
    {
        float* tile = W2s;                        // [32][33]
        int tx = tid & 31, ty8 = tid >> 5;        // ty8: 0..7
        for (;;) {
            if (tid == 0) tno = atomicAdd(&g_tick, 1);
            __syncthreads();
            int t = tno;
            if (t >= NTILES) break;
            int tb  = t >> 8;
            int rem = t & 255;
            int c0  = (rem & 3) * 32, n0 = (rem >> 2) * 32;
            const float* srcf = feat + (size_t)tb * Cn * Nn;
            float* dst = g_featT + (size_t)tb * Nn * Cn;
#pragma unroll
            for (int j = 0; j < 32; j += 8)
                tile[(ty8 + j)*33 + tx] = srcf[(size_t)(c0 + ty8 + j) * Nn + n0 + tx];
            __syncthreads();
#pragma unroll
            for (int j = 0; j < 32; j += 8)
                dst[(size_t)(n0 + ty8 + j) * Cn + c0 + tx] = tile[tx*33 + ty8 + j];
            __syncthreads();
            if (tid == 0) {
                __threadfence();
                atomicAdd((int*)&g_tdone, 1);
            }
        }
    }
    __syncthreads();

    // ---- load weights into smem (overwrites tile region; all tiles done here)
    for (int i = tid; i < 320; i += 256) W1s[i] = W1[i];
    if (tid < 32) b1s[tid] = b1[tid];
    for (int i = tid; i < 32*CPW2; i += 256) {
        int m = i / CPW2, c = i - m * CPW2;
        W2s[i] = (c < CIN) ? W2[m*CIN + c] : 0.f;
    }
    for (int i = tid; i < CPW2; i += 256) b2s[i] = (i < CIN) ? b2[i] : 0.f;
    for (int i = tid; i < 3*132; i += 256) pooled_sh[i] = 0;

    // ---- wait for our center to be produced
    if (tid == 0) {
        while (g_prog[b] <= p) __nanosleep(128);
        __threadfence();
    }
    __syncthreads();

    float cx = out_xyz[(size_t)blk*3 + 0];
    float cy = out_xyz[(size_t)blk*3 + 1];
    float cz = out_xyz[(size_t)blk*3 + 2];

    // ---- ball query (warps 0-2)
    if (w < 3) {
        const float thr = (w == 0) ? (float)(0.1*0.1) : (w == 1) ? (float)(0.2*0.2) : (float)(0.4*0.4);
        const int   ns  = (w == 0) ? 16 : (w == 1) ? 32 : 48;
        const int   off = (w == 0) ? 0  : (w == 1) ? 16 : 48;
        int cnt = 0;
        for (int ch = 0; ch < 64 && cnt < ns; ++ch) {
            int i = ch*32 + lane;
            float qx = bp[i*3 + 0], qy = bp[i*3 + 1], qz = bp[i*3 + 2];
            float ax = cx - qx, ay = cy - qy, az = cz - qz;
            float d2 = __fadd_rn(__fadd_rn(__fmul_rn(ax,ax), __fmul_rn(ay,ay)), __fmul_rn(az,az));
            bool pr = d2 < thr;
            unsigned mk = __ballot_sync(0xffffffffu, pr);
            if (pr) {
                int pos = cnt + __popc(mk & ((1u << lane) - 1u));
                if (pos < ns) idx_sh[off + pos] = i;
            }
            cnt += __popc(mk);
        }
        __syncwarp();
        if (cnt < ns) {
            int f0 = idx_sh[off];
            for (int q = cnt + lane; q < ns; q += 32) idx_sh[off + q] = f0;
        }
    }

    // ---- wait for featT complete (normally already done)
    if (tid == 0) {
        while (g_tdone < NTILES) __nanosleep(128);
        __threadfence();
    }
    __syncthreads();

    // ---- MLP + pooling: 24 groups of 4 samples over 8 warps
    const float* ftb = g_featT + (size_t)b * Nn * Cn;
    for (int g = w; g < 24; g += 8) {
        int s, sb, j0;
        if (g < 4)       { s = 0; sb = 0;  j0 = g * 4; }
        else if (g < 12) { s = 1; sb = 16; j0 = (g - 4) * 4; }
        else             { s = 2; sb = 48; j0 = (g - 12) * 4; }
        int sidx[4]; float relx[4], rely[4], relz[4], h1v[4];
#pragma unroll
        for (int q = 0; q < 4; ++q) {
            int ii = idx_sh[sb + j0 + q];
            sidx[q] = ii;
            float gx = bp[ii*3 + 0], gy = bp[ii*3 + 1], gz = bp[ii*3 + 2];
            float rx = gx - cx, ry = gy - cy, rz = gz - cz;
            relx[q] = rx; rely[q] = ry; relz[q] = rz;
            float dn = sqrtf(rx*rx + ry*ry + rz*rz);
            float a = b1s[lane];
            a = fmaf(dn, W1s[0*32 + lane], a);
            a = fmaf(cx, W1s[1*32 + lane], a);
            a = fmaf(cy, W1s[2*32 + lane], a);
            a = fmaf(cz, W1s[3*32 + lane], a);
            a = fmaf(gx, W1s[4*32 + lane], a);
            a = fmaf(gy, W1s[5*32 + lane], a);
            a = fmaf(gz, W1s[6*32 + lane], a);
            a = fmaf(rx, W1s[7*32 + lane], a);
            a = fmaf(ry, W1s[8*32 + lane], a);
            a = fmaf(rz, W1s[9*32 + lane], a);
            h1v[q] = fmaxf(a, 0.f);
        }
        __syncwarp();
        *(float4*)&h1buf[(w*32 + lane)*4] = make_float4(h1v[0], h1v[1], h1v[2], h1v[3]);
        __syncwarp();

        float acc[5][4];
#pragma unroll
        for (int i = 0; i < 5; ++i) {
            float bb = b2s[i*32 + lane];
            acc[i][0] = bb; acc[i][1] = bb; acc[i][2] = bb; acc[i][3] = bb;
        }
#pragma unroll 4
        for (int m = 0; m < 32; ++m) {
            float4 H = *(const float4*)&h1buf[(w*32 + m)*4];
#pragma unroll
            for (int i = 0; i < 5; ++i) {
                float ww = W2s[m*CPW2 + i*32 + lane];
                acc[i][0] = fmaf(ww, H.x, acc[i][0]);
                acc[i][1] = fmaf(ww, H.y, acc[i][1]);
                acc[i][2] = fmaf(ww, H.z, acc[i][2]);
                acc[i][3] = fmaf(ww, H.w, acc[i][3]);
            }
        }
#pragma unroll
        for (int i = 0; i < 5; ++i) {
            int c = i*32 + lane;
            if (c < CIN) {
                float vmax = 0.f;
#pragma unroll
                for (int q = 0; q < 4; ++q) {
                    float xv;
                    if (c >= 3) xv = ftb[(size_t)sidx[q]*Cn + (c - 3)];
                    else        xv = (c == 0) ? relx[q] : (c == 1) ? rely[q] : relz[q];
                    float v = acc[i][q] * xv;
                    vmax = fmaxf(vmax, fmaxf(v, 0.f));
                }
                atomicMax(&pooled_sh[s*132 + c], __float_as_int(vmax)); // vmax >= 0
            }
        }
    }
    __syncthreads();
    for (int i = tid; i < 3*CIN; i += 256) {
        int s = i / CIN, c = i - s*CIN;
        g_pooled[(size_t)(s*8192 + blk)*PROW + c] = __int_as_float(pooled_sh[s*132 + c]);
    }
}

// ---------------------------------------------------------------------------
// K3: relu(pooled @ Wcr + bcr), tiled GEMM. Also resets the sync state so the
// next graph replay starts clean (stream-ordered after k_main completes).
// ---------------------------------------------------------------------------
__global__ __launch_bounds__(256) void k_proj(const float* __restrict__ Wcr,
                                              const float* __restrict__ bcr,
                                              float* __restrict__ outF) {
    if (blockIdx.x == 0 && threadIdx.x == 0) {
        g_tick = 0;
        g_tdone = 0;
#pragma unroll
        for (int i = 0; i < Bn; ++i) g_prog[i] = 0;
    }
    __shared__ float Ps[131*36];
    __shared__ float Wp[32*128];
    __shared__ float bs[128];
    int tid = threadIdx.x;
    int row0 = blockIdx.x * 32;
    for (int idx = tid; idx < 32*131; idx += 256) {
        int r = idx / 131, k = idx - r*131;
        Ps[k*36 + r] = g_pooled[(size_t)(row0 + r)*PROW + k];
    }
    if (tid < 128) bs[tid] = bcr[tid];
    float acc[4][4];
#pragma unroll
    for (int r = 0; r < 4; ++r)
#pragma unroll
        for (int o = 0; o < 4; ++o) acc[r][o] = 0.f;
    int cg = tid & 31, rg = tid >> 5;
    for (int kp = 0; kp < 5; ++kp) {
        int kb = kp*32;
        int klen = (kp == 4) ? 3 : 32;
        __syncthreads();
        for (int idx = tid; idx < klen*128; idx += 256) Wp[idx] = Wcr[kb*128 + idx];
        __syncthreads();
        for (int kk = 0; kk < klen; ++kk) {
            float4 wv = *(const float4*)&Wp[kk*128 + cg*4];
            float4 av = *(const float4*)&Ps[(kb + kk)*36 + rg*4];
            acc[0][0] = fmaf(av.x, wv.x, acc[0][0]);
            acc[0][1] = fmaf(av.x, wv.y, acc[0][1]);
            acc[0][2] = fmaf(av.x, wv.z, acc[0][2]);
            acc[0][3] = fmaf(av.x, wv.w, acc[0][3]);
            acc[1][0] = fmaf(av.y, wv.x, acc[1][0]);
            acc[1][1] = fmaf(av.y, wv.y, acc[1][1]);
            acc[1][2] = fmaf(av.y, wv.z, acc[1][2]);
            acc[1][3] = fmaf(av.y, wv.w, acc[1][3]);
            acc[2][0] = fmaf(av.z, wv.x, acc[2][0]);
            acc[2][1] = fmaf(av.z, wv.y, acc[2][1]);
            acc[2][2] = fmaf(av.z, wv.z, acc[2][2]);
            acc[2][3] = fmaf(av.z, wv.w, acc[2][3]);
            acc[3][0] = fmaf(av.w, wv.x, acc[3][0]);
            acc[3][1] = fmaf(av.w, wv.y, acc[3][1]);
            acc[3][2] = fmaf(av.w, wv.z, acc[3][2]);
            acc[3][3] = fmaf(av.w, wv.w, acc[3][3]);
        }
    }
#pragma unroll
    for (int rr = 0; rr < 4; ++rr) {
        int row = row0 + rg*4 + rr;
        int s  = row >> 13;
        int bb = (row >> 9) & 15;
        int pp = row & 511;
        size_t obase = (size_t)bb*(384*512) + (size_t)(s*128)*512 + pp;
#pragma unroll
        for (int oo = 0; oo < 4; ++oo) {
            float v = acc[rr][oo] + bs[cg*4 + oo];
            outF[obase + (size_t)(cg*4 + oo)*512] = fmaxf(v, 0.f);
        }
    }
}

// ---------------------------------------------------------------------------
extern "C" void kernel_launch(void* const* d_in, const int* in_sizes, int n_in,
                              void* d_out, int out_size) {
    const float* xyz  = (const float*)d_in[0];
    const float* feat = (const float*)d_in[1];
    const float* W1   = (const float*)d_in[2];
    const float* b1   = (const float*)d_in[3];
    const float* W2   = (const float*)d_in[4];
    const float* b2   = (const float*)d_in[5];
    const float* Wcr  = (const float*)d_in[6];
    const float* bcr  = (const float*)d_in[7];
    float* out      = (float*)d_out;
    float* out_xyz  = out;                 // (B,512,3)
    float* outF     = out + Bn*NP*3;       // (B,384,512)

    k_main<<<16 + 8192, 256>>>(xyz, feat, W1, b1, W2, b2, out_xyz);
    k_proj<<<768, 256>>>(Wcr, bcr, outF);
}

// round 6
// speedup vs baseline: 1.7678x; 1.7678x over previous
#include <cuda_runtime.h>
#include <cstddef>

#define Bn 16
#define Nn 2048
#define Cn 128
#define NP 512
#define CIN 131
#define CPW2 160
#define PROW 132
#define NROWS (3*Bn*NP)
#define NTILES 4096
#define NCTR   8192
#define NTASK  (NTILES + NCTR)
#define NWORK  768

__device__ float g_featT[Bn*Nn*Cn];
__device__ float g_pooled[NROWS*PROW];
__device__ volatile int g_prog[Bn];   // FPS progress per batch (zero-init)
__device__ int g_task = 0;            // global ticket
__device__ volatile int g_tdone = 0;  // transpose tiles completed

// smem overlay (floats):
//  worker: W2s[0,5120) b2s[5120,5280) W1s[5280,5600) b1s[5600,5632)
//          u_buf[5632,6688) (tile 1056 | h1buf 1024)
//          masks[6688,6880) idx[6880,6976) pooled[6976,7372) tno@7372
//  fps:    xs[0,2048) ys[2048,4096) zs[4096,6144) rvb/rib[6144,6176)
#define SMEMF 7376

__global__ __launch_bounds__(256) void k_main(const float* __restrict__ xyz,
                                              const float* __restrict__ feat,
                                              const float* __restrict__ W1,
                                              const float* __restrict__ b1,
                                              const float* __restrict__ W2,
                                              const float* __restrict__ b2,
                                              float* __restrict__ out_xyz) {
    __shared__ __align__(16) float smem_f[SMEMF];
    int tid = threadIdx.x, lane = tid & 31, w = tid >> 5;

    if (blockIdx.x < 16) {
        // ================= FPS (one block per batch, 8 pts/thread) =========
        float* xs = smem_f;
        float* ys = smem_f + 2048;
        float* zs = smem_f + 4096;
        unsigned* rvb = (unsigned*)(smem_f + 6144);   // [2][8]
        int*      rib = (int*)(smem_f + 6160);        // [2][8]
        int b = blockIdx.x;
        const float* src = xyz + (size_t)b * Nn * 3;
        for (int t = tid; t < Nn; t += 256) {
            xs[t] = src[t*3 + 0]; ys[t] = src[t*3 + 1]; zs[t] = src[t*3 + 2];
        }
        __syncthreads();
        float X[8], Y[8], Z[8], D[8];
#pragma unroll
        for (int q = 0; q < 8; ++q) {
            int i = tid*8 + q;
            X[q] = xs[i]; Y[q] = ys[i]; Z[q] = zs[i];
            D[q] = 1e10f;
        }
        int last = 0;
        if (tid == 0) {
            out_xyz[(size_t)b*NP*3 + 0] = xs[0];
            out_xyz[(size_t)b*NP*3 + 1] = ys[0];
            out_xyz[(size_t)b*NP*3 + 2] = zs[0];
        }
        for (int it = 1; it < NP; ++it) {
            float px = xs[last], py = ys[last], pz = zs[last];
#pragma unroll
            for (int q = 0; q < 8; ++q) {
                float ax = X[q] - px, ay = Y[q] - py, az = Z[q] - pz;
                float dd = __fadd_rn(__fadd_rn(__fmul_rn(ax,ax), __fmul_rn(ay,ay)),
                                     __fmul_rn(az,az));
                D[q] = fminf(D[q], dd);
            }
            float va = D[0]; int ia = 0;
            if (D[1] > va) { va = D[1]; ia = 1; }
            float vb = D[2]; int ib = 2;
            if (D[3] > vb) { vb = D[3]; ib = 3; }
            float vc = D[4]; int ic = 4;
            if (D[5] > vc) { vc = D[5]; ic = 5; }
            float vd = D[6]; int id_ = 6;
            if (D[7] > vd) { vd = D[7]; id_ = 7; }
            if (vb > va) { va = vb; ia = ib; }
            if (vd > vc) { vc = vd; ic = id_; }
            if (vc > va) { va = vc; ia = ic; }
            unsigned bits = __float_as_uint(va);
            unsigned m = __reduce_max_sync(0xffffffffu, bits);
            unsigned bal = __ballot_sync(0xffffffffu, bits == m);
            int srcl = __ffs(bal) - 1;
            int lloc = __shfl_sync(0xffffffffu, ia, srcl);
            int bufi = it & 1;
            if (lane == 0) {
                rvb[bufi*8 + w] = m;
                rib[bufi*8 + w] = (w*32 + srcl)*8 + lloc;
            }
            __syncthreads();
            int j = lane & 7;
            unsigned v2 = rvb[bufi*8 + j];
            int      i2 = rib[bufi*8 + j];
            unsigned m2 = __reduce_max_sync(0xffffffffu, v2);
            unsigned b2_ = __ballot_sync(0xffffffffu, v2 == m2);
            int s2 = __ffs(b2_) - 1;
            last = __shfl_sync(0xffffffffu, i2, s2);
            if (tid == 0) {
                out_xyz[(size_t)(b*NP + it)*3 + 0] = xs[last];
                out_xyz[(size_t)(b*NP + it)*3 + 1] = ys[last];
                out_xyz[(size_t)(b*NP + it)*3 + 2] = zs[last];
                if ((it & 3) == 3 || it == NP-1) {
                    __threadfence();
                    g_prog[b] = it + 1;
                }
            }
        }
        return;
    }

    // ================= persistent worker ===================================
    float* W2s    = smem_f;
    float* b2s    = smem_f + 5120;
    float* W1s    = smem_f + 5280;
    float* b1s    = smem_f + 5600;
    float* u_buf  = smem_f + 5632;             // tile(1056) | h1buf(1024)
    unsigned* masks = (unsigned*)(smem_f + 6688);  // [3][64]
    int*  idx_sh  = (int*)(smem_f + 6880);     // [96]
    int*  pooled  = (int*)(smem_f + 6976);     // [396]
    int*  tno     = (int*)(smem_f + 7372);

    // load weights once per worker
    for (int i = tid; i < 32*CPW2; i += 256) {
        int m = i / CPW2, c = i - m * CPW2;
        W2s[i] = (c < CIN) ? W2[m*CIN + c] : 0.f;
    }
    for (int i = tid; i < CPW2; i += 256) b2s[i] = (i < CIN) ? b2[i] : 0.f;
    for (int i = tid; i < 320; i += 256) W1s[i] = W1[i];
    if (tid < 32) b1s[tid] = b1[tid];

    for (;;) {
        if (tid == 0) *tno = atomicAdd(&g_task, 1);
        __syncthreads();
        int t = *tno;
        if (t >= NTASK) break;

        if (t < NTILES) {
            // ---- transpose tile (b-fastest order) into u_buf[32][33]
            int tb  = t & 15;
            int rem = t >> 4;
            int c0  = (rem & 3) * 32, n0 = (rem >> 2) * 32;
            int tx = tid & 31, ty8 = tid >> 5;
            const float* srcf = feat + (size_t)tb * Cn * Nn;
            float* dst = g_featT + (size_t)tb * Nn * Cn;
#pragma unroll
            for (int j = 0; j < 32; j += 8)
                u_buf[(ty8 + j)*33 + tx] = srcf[(size_t)(c0 + ty8 + j) * Nn + n0 + tx];
            __syncthreads();
#pragma unroll
            for (int j = 0; j < 32; j += 8)
                dst[(size_t)(n0 + ty8 + j) * Cn + c0 + tx] = u_buf[tx*33 + ty8 + j];
            __syncthreads();
            if (tid == 0) {
                __threadfence();
                atomicAdd((int*)&g_tdone, 1);
            }
            continue;
        }

        // ---- center task: b-fastest ordering matches FPS production
        int ct = t - NTILES;
        int b = ct & 15, p = ct >> 4;
        int blk = b*NP + p;
        const float* bp = xyz + (size_t)b * Nn * 3;

        for (int i = tid; i < 396; i += 256) pooled[i] = 0;
        if (tid == 0) {
            while (g_prog[b] <= p || g_tdone < NTILES) __nanosleep(64);
            __threadfence();
        }
        __syncthreads();

        float cx = out_xyz[(size_t)blk*3 + 0];
        float cy = out_xyz[(size_t)blk*3 + 1];
        float cz = out_xyz[(size_t)blk*3 + 2];

        // ---- phase A: one pass, d2 once, 3 ballots per chunk
        {
            int chunk0 = w*8;
#pragma unroll
            for (int j = 0; j < 8; ++j) {
                int i = (chunk0 + j)*32 + lane;
                float qx = bp[i*3 + 0], qy = bp[i*3 + 1], qz = bp[i*3 + 2];
                float ax = cx - qx, ay = cy - qy, az = cz - qz;
                float d2 = __fadd_rn(__fadd_rn(__fmul_rn(ax,ax), __fmul_rn(ay,ay)),
                                     __fmul_rn(az,az));
                unsigned m0 = __ballot_sync(0xffffffffu, d2 < (float)(0.1*0.1));
                unsigned m1 = __ballot_sync(0xffffffffu, d2 < (float)(0.2*0.2));
                unsigned m2 = __ballot_sync(0xffffffffu, d2 < (float)(0.4*0.4));
                if (lane == 0) {
                    masks[0*64 + chunk0 + j] = m0;
                    masks[1*64 + chunk0 + j] = m1;
                    masks[2*64 + chunk0 + j] = m2;
                }
            }
        }
        __syncthreads();

        // ---- phase B: warps 0-2 extract first-ns ascending indices
        if (w < 3) {
            const int ns  = (w == 0) ? 16 : (w == 1) ? 32 : 48;
            const int off = (w == 0) ? 0  : (w == 1) ? 16 : 48;
            const unsigned* MM = masks + w*64;
            unsigned ma = MM[lane], mb = MM[lane + 32];
            int pa = __popc(ma), pb = __popc(mb);
            int sa = pa;
#pragma unroll
            for (int d = 1; d < 32; d <<= 1) {
                int n = __shfl_up_sync(0xffffffffu, sa, d);
                if (lane >= d) sa += n;
            }
            int totA = __shfl_sync(0xffffffffu, sa, 31);
            int sb_ = pb;
#pragma unroll
            for (int d = 1; d < 32; d <<= 1) {
                int n = __shfl_up_sync(0xffffffffu, sb_, d);
                if (lane >= d) sb_ += n;
            }
            int cnt = totA + __shfl_sync(0xffffffffu, sb_, 31);
            int pos = sa - pa;              // exclusive base, first half
            unsigned m = ma; int cb = lane*32;
            while (m && pos < ns) {
                int bix = __ffs(m) - 1;
                idx_sh[off + pos] = cb + bix;
                m &= m - 1; ++pos;
            }
            pos = totA + sb_ - pb;          // exclusive base, second half
            m = mb; cb = (lane + 32)*32;
            while (m && pos < ns) {
                int bix = __ffs(m) - 1;
                idx_sh[off + pos] = cb + bix;
                m &= m - 1; ++pos;
            }
            __syncwarp();
            if (cnt < ns) {
                int f0 = idx_sh[off];
                for (int q = cnt + lane; q < ns; q += 32) idx_sh[off + q] = f0;
            }
        }
        __syncthreads();

        // ---- MLP + pooling: 24 groups of 4 samples over 8 warps
        float* h1buf = u_buf;
        const float* ftb = g_featT + (size_t)b * Nn * Cn;
        for (int g = w; g < 24; g += 8) {
            int s, sb, j0;
            if (g < 4)       { s = 0; sb = 0;  j0 = g * 4; }
            else if (g < 12) { s = 1; sb = 16; j0 = (g - 4) * 4; }
            else             { s = 2; sb = 48; j0 = (g - 12) * 4; }
            int sidx[4]; float relx[4], rely[4], relz[4], h1v[4];
#pragma unroll
            for (int q = 0; q < 4; ++q) {
                int ii = idx_sh[sb + j0 + q];
                sidx[q] = ii;
                float gx = bp[ii*3 + 0], gy = bp[ii*3 + 1], gz = bp[ii*3 + 2];
                float rx = gx - cx, ry = gy - cy, rz = gz - cz;
                relx[q] = rx; rely[q] = ry; relz[q] = rz;
                float dn = sqrtf(rx*rx + ry*ry + rz*rz);
                float a = b1s[lane];
                a = fmaf(dn, W1s[0*32 + lane], a);
                a = fmaf(cx, W1s[1*32 + lane], a);
                a = fmaf(cy, W1s[2*32 + lane], a);
                a = fmaf(cz, W1s[3*32 + lane], a);
                a = fmaf(gx, W1s[4*32 + lane], a);
                a = fmaf(gy, W1s[5*32 + lane], a);
                a = fmaf(gz, W1s[6*32 + lane], a);
                a = fmaf(rx, W1s[7*32 + lane], a);
                a = fmaf(ry, W1s[8*32 + lane], a);
                a = fmaf(rz, W1s[9*32 + lane], a);
                h1v[q] = fmaxf(a, 0.f);
            }
            __syncwarp();
            *(float4*)&h1buf[(w*32 + lane)*4] = make_float4(h1v[0], h1v[1], h1v[2], h1v[3]);
            __syncwarp();

            float acc[5][4];
#pragma unroll
            for (int i = 0; i < 5; ++i) {
                float bb = b2s[i*32 + lane];
                acc[i][0] = bb; acc[i][1] = bb; acc[i][2] = bb; acc[i][3] = bb;
            }
#pragma unroll 4
            for (int m = 0; m < 32; ++m) {
                float4 H = *(const float4*)&h1buf[(w*32 + m)*4];
#pragma unroll
                for (int i = 0; i < 5; ++i) {
                    float ww = W2s[m*CPW2 + i*32 + lane];
                    acc[i][0] = fmaf(ww, H.x, acc[i][0]);
                    acc[i][1] = fmaf(ww, H.y, acc[i][1]);
                    acc[i][2] = fmaf(ww, H.z, acc[i][2]);
                    acc[i][3] = fmaf(ww, H.w, acc[i][3]);
                }
            }
#pragma unroll
            for (int i = 0; i < 5; ++i) {
                int c = i*32 + lane;
                if (c < CIN) {
                    float vmax = 0.f;
#pragma unroll
                    for (int q = 0; q < 4; ++q) {
                        float xv;
                        if (c >= 3) xv = ftb[(size_t)sidx[q]*Cn + (c - 3)];
                        else        xv = (c == 0) ? relx[q] : (c == 1) ? rely[q] : relz[q];
                        float v = acc[i][q] * xv;
                        vmax = fmaxf(vmax, fmaxf(v, 0.f));
                    }
                    atomicMax(&pooled[s*132 + c], __float_as_int(vmax)); // vmax >= 0
                }
            }
        }
        __syncthreads();
        for (int i = tid; i < 3*CIN; i += 256) {
            int s = i / CIN, c = i - s*CIN;
            g_pooled[(size_t)(s*8192 + blk)*PROW + c] = __int_as_float(pooled[s*132 + c]);
        }
        __syncthreads();
    }
}

// ---------------------------------------------------------------------------
// K3: relu(pooled @ Wcr + bcr), tiled GEMM. Also resets sync state for the
// next graph replay (stream-ordered after k_main).
// ---------------------------------------------------------------------------
__global__ __launch_bounds__(256) void k_proj(const float* __restrict__ Wcr,
                                              const float* __restrict__ bcr,
                                              float* __restrict__ outF) {
    if (blockIdx.x == 0 && threadIdx.x == 0) {
        g_task = 0;
        g_tdone = 0;
#pragma unroll
        for (int i = 0; i < Bn; ++i) g_prog[i] = 0;
    }
    __shared__ float Ps[131*36];
    __shared__ float Wp[32*128];
    __shared__ float bs[128];
    int tid = threadIdx.x;
    int row0 = blockIdx.x * 32;
    for (int idx = tid; idx < 32*131; idx += 256) {
        int r = idx / 131, k = idx - r*131;
        Ps[k*36 + r] = g_pooled[(size_t)(row0 + r)*PROW + k];
    }
    if (tid < 128) bs[tid] = bcr[tid];
    float acc[4][4];
#pragma unroll
    for (int r = 0; r < 4; ++r)
#pragma unroll
        for (int o = 0; o < 4; ++o) acc[r][o] = 0.f;
    int cg = tid & 31, rg = tid >> 5;
    for (int kp = 0; kp < 5; ++kp) {
        int kb = kp*32;
        int klen = (kp == 4) ? 3 : 32;
        __syncthreads();
        for (int idx = tid; idx < klen*128; idx += 256) Wp[idx] = Wcr[kb*128 + idx];
        __syncthreads();
        for (int kk = 0; kk < klen; ++kk) {
            float4 wv = *(const float4*)&Wp[kk*128 + cg*4];
            float4 av = *(const float4*)&Ps[(kb + kk)*36 + rg*4];
            acc[0][0] = fmaf(av.x, wv.x, acc[0][0]);
            acc[0][1] = fmaf(av.x, wv.y, acc[0][1]);
            acc[0][2] = fmaf(av.x, wv.z, acc[0][2]);
            acc[0][3] = fmaf(av.x, wv.w, acc[0][3]);
            acc[1][0] = fmaf(av.y, wv.x, acc[1][0]);
            acc[1][1] = fmaf(av.y, wv.y, acc[1][1]);
            acc[1][2] = fmaf(av.y, wv.z, acc[1][2]);
            acc[1][3] = fmaf(av.y, wv.w, acc[1][3]);
            acc[2][0] = fmaf(av.z, wv.x, acc[2][0]);
            acc[2][1] = fmaf(av.z, wv.y, acc[2][1]);
            acc[2][2] = fmaf(av.z, wv.z, acc[2][2]);
            acc[2][3] = fmaf(av.z, wv.w, acc[2][3]);
            acc[3][0] = fmaf(av.w, wv.x, acc[3][0]);
            acc[3][1] = fmaf(av.w, wv.y, acc[3][1]);
            acc[3][2] = fmaf(av.w, wv.z, acc[3][2]);
            acc[3][3] = fmaf(av.w, wv.w, acc[3][3]);
        }
    }
#pragma unroll
    for (int rr = 0; rr < 4; ++rr) {
        int row = row0 + rg*4 + rr;
        int s  = row >> 13;
        int bb = (row >> 9) & 15;
        int pp = row & 511;
        size_t obase = (size_t)bb*(384*512) + (size_t)(s*128)*512 + pp;
#pragma unroll
        for (int oo = 0; oo < 4; ++oo) {
            float v = acc[rr][oo] + bs[cg*4 + oo];
            outF[obase + (size_t)(cg*4 + oo)*512] = fmaxf(v, 0.f);
        }
    }
}

// ---------------------------------------------------------------------------
extern "C" void kernel_launch(void* const* d_in, const int* in_sizes, int n_in,
                              void* d_out, int out_size) {
    const float* xyz  = (const float*)d_in[0];
    const float* feat = (const float*)d_in[1];
    const float* W1   = (const float*)d_in[2];
    const float* b1   = (const float*)d_in[3];
    const float* W2   = (const float*)d_in[4];
    const float* b2   = (const float*)d_in[5];
    const float* Wcr  = (const float*)d_in[6];
    const float* bcr  = (const float*)d_in[7];
    float* out      = (float*)d_out;
    float* out_xyz  = out;                 // (B,512,3)
    float* outF     = out + Bn*NP*3;       // (B,384,512)

    k_main<<<16 + NWORK, 256>>>(xyz, feat, W1, b1, W2, b2, out_xyz);
    k_proj<<<768, 256>>>(Wcr, bcr, outF);
}